// round 12
// baseline (speedup 1.0000x reference)
#include <cuda_runtime.h>
#include <math.h>

#define S_  512
#define L_  128
#define D_  256
#define H2_ 128
#define P_  16
#define B_  128
#define F_  256
#define FEAT_ 640
#define ED_ 64
#define GRID_ 256
#define NT_ 256

typedef unsigned long long u64;

// Scratch (device globals — no allocations allowed)
__device__ float g_attwT[D_ * H2_];       // [d][h]
__device__ float g_logpart[2][B_ * 32];   // per-half partial logits
__device__ float g_featsT[FEAT_ * B_];    // [k][b]
__device__ unsigned g_bar;                // zero-init; monotonic across replays

__device__ __forceinline__ u64 pack2(float x, float y) {
    u64 r; asm("mov.b64 %0, {%1, %2};" : "=l"(r) : "f"(x), "f"(y)); return r;
}
__device__ __forceinline__ void unpack2(u64 v, float& x, float& y) {
    asm("mov.b64 {%0, %1}, %2;" : "=f"(x), "=f"(y) : "l"(v));
}
__device__ __forceinline__ void fma2(u64& d, u64 a, u64 b) {
    asm("fma.rn.f32x2 %0, %1, %2, %0;" : "+l"(d) : "l"(a), "l"(b));
}

__device__ __forceinline__ void grid_sync() {
    __syncthreads();
    if (threadIdx.x == 0) {
        __threadfence();
        unsigned ticket = atomicAdd(&g_bar, 1u);
        unsigned target = (ticket / GRID_ + 1u) * GRID_;
        volatile unsigned* p = &g_bar;
        while (*p < target) { }
        __threadfence();
    }
    __syncthreads();
}

__global__ __launch_bounds__(NT_, 2) void fused_all(
    const int* __restrict__ x,        // [S, L]
    const int* __restrict__ ents,     // [B, 2]
    const int* __restrict__ spos,     // [B, P, 2]
    const int* __restrict__ tpos,     // [B, P, 2]
    const float* __restrict__ emb,    // [V, D]
    const float* __restrict__ ent_emb,// [E_V, ED]
    const float* __restrict__ attw_W, // [H2, D]
    const float* __restrict__ attw_b, // [H2]
    const float* __restrict__ attw2_W,// [1, H2]
    const float* __restrict__ cond_W, // [F, FEAT]
    const float* __restrict__ cond_b, // [F]
    const float* __restrict__ lin_W,  // [2, F]
    const float* __restrict__ lin_b,  // [2]
    float* __restrict__ out)          // [B, 2]
{
    extern __shared__ float sm[];
    const int cta = blockIdx.x, tid = threadIdx.x;
    const int wi = tid >> 5, lane = tid & 31;

    __shared__ int   toks[32];
    __shared__ float part[32][9];
    __shared__ float wgt[16];
    __shared__ u64   sp2[8][32];

    // ============ Phase 0: transpose attw_W (coalesced reads) + zero out ====
    {
        int gt = cta * NT_ + tid, gs = GRID_ * NT_;
        for (int i = gt; i < H2_ * D_; i += gs) {       // i = h*256 + d
            int h = i >> 8, d = i & 255;
            g_attwT[d * H2_ + h] = attw_W[i];
        }
        if (gt < 2 * B_) out[gt] = 0.0f;
    }
    grid_sync();

    // ============ Phase 1a: pool energies (2 CTAs per b, 64 cols each) ======
    const int b = cta >> 1, half = cta & 1;
    float* ws = sm;                  // [256 d][64 h-half]
    float* Hm = sm + D_ * 64;        // [32][257]  rows 0-15 s, 16-31 t

    if (tid < 32) {
        int pool = tid >> 4, p = tid & 15;
        const int* pos = pool ? tpos : spos;
        int s = pos[(b * P_ + p) * 2 + 0];
        int l = pos[(b * P_ + p) * 2 + 1];
        toks[tid] = x[s * L_ + l];
    }
    // stage this half's 64 cols of attwT (64 KB), coalesced
    {
        const float4* src = reinterpret_cast<const float4*>(g_attwT) + half * 16;
        float4* dst = reinterpret_cast<float4*>(ws);
        #pragma unroll
        for (int j = 0; j < 16; j++) {
            int i = tid + NT_ * j;            // 4096 float4
            int d = i >> 4, hh4 = i & 15;
            dst[i] = src[d * 32 + hh4];
        }
    }
    __syncthreads();
    // gather 32 embedding rows (coalesced per row)
    #pragma unroll
    for (int j = 0; j < 32; j++) {
        int i = tid + NT_ * j;                // 8192 items
        int r = i >> 8, d = i & 255;
        Hm[r * 257 + d] = emb[(size_t)toks[r] * D_ + d];
    }
    __syncthreads();

    {
        // row = lane (32 rows), warp -> 8 local cols
        const int col0 = half * 64 + wi * 8;
        const float* wrow = ws + wi * 8;
        const float* hrow = Hm + lane * 257;
        u64 a0 = 0ull, a1 = 0ull, a2 = 0ull, a3 = 0ull;
        #pragma unroll 8
        for (int d = 0; d < D_; d++) {
            float a = hrow[d];
            u64 ap = pack2(a, a);
            const ulonglong2* wq = reinterpret_cast<const ulonglong2*>(wrow + d * 64);
            ulonglong2 q0 = wq[0], q1 = wq[1];
            fma2(a0, ap, q0.x); fma2(a1, ap, q0.y);
            fma2(a2, ap, q1.x); fma2(a3, ap, q1.y);
        }
        float cs_ = 0.f, e0, e1;
        unpack2(a0, e0, e1);
        cs_ += tanhf(e0 + attw_b[col0+0]) * attw2_W[col0+0]
             + tanhf(e1 + attw_b[col0+1]) * attw2_W[col0+1];
        unpack2(a1, e0, e1);
        cs_ += tanhf(e0 + attw_b[col0+2]) * attw2_W[col0+2]
             + tanhf(e1 + attw_b[col0+3]) * attw2_W[col0+3];
        unpack2(a2, e0, e1);
        cs_ += tanhf(e0 + attw_b[col0+4]) * attw2_W[col0+4]
             + tanhf(e1 + attw_b[col0+5]) * attw2_W[col0+5];
        unpack2(a3, e0, e1);
        cs_ += tanhf(e0 + attw_b[col0+6]) * attw2_W[col0+6]
             + tanhf(e1 + attw_b[col0+7]) * attw2_W[col0+7];
        part[lane][wi] = cs_;
    }
    __syncthreads();
    if (tid < 32) {
        float s = 0.f;
        #pragma unroll
        for (int q = 0; q < 8; q++) s += part[tid][q];
        g_logpart[half][b * 32 + tid] = s;
    }
    grid_sync();

    // ============ Phase 1b: softmax + pooled feats (this CTA: pool = half) ==
    if (tid == 0) {
        int base = b * 32 + half * 16;
        float lg[16];
        #pragma unroll
        for (int p = 0; p < 16; p++) lg[p] = g_logpart[0][base + p] + g_logpart[1][base + p];
        float mx = lg[0];
        #pragma unroll
        for (int p = 1; p < 16; p++) mx = fmaxf(mx, lg[p]);
        float e[16]; float sum = 0.f;
        #pragma unroll
        for (int p = 0; p < 16; p++) { e[p] = __expf(lg[p] - mx); sum += e[p]; }
        float inv = 1.f / sum;
        #pragma unroll
        for (int p = 0; p < 16; p++) wgt[p] = e[p] * inv;
    }
    __syncthreads();
    {
        const float* hp = Hm + half * 16 * 257 + tid;
        float v = 0.f;
        #pragma unroll
        for (int p = 0; p < 16; p++) v += wgt[p] * hp[p * 257];
        g_featsT[(half * D_ + tid) * B_ + b] = v;
    }
    if (half == 0 && tid < 128) {
        int eidx = ents[b * 2 + (tid >> 6)];
        g_featsT[(2 * D_ + tid) * B_ + b] = ent_emb[(size_t)eidx * ED_ + (tid & 63)];
    }
    grid_sync();

    // ============ Phase 2: gemm tile 4b x 32f + fused head ==================
    {
        const int bt = cta >> 3, ft = cta & 7;
        const int b0 = bt * 4, f0 = ft * 32;
        float* fs  = sm;                 // [640][4]
        float* cst = sm + FEAT_ * 4;     // [640][33]

        #pragma unroll
        for (int j = 0; j < 10; j++) {
            int i = tid + NT_ * j;       // 2560 items: k=i>>2, bb=i&3
            fs[i] = g_featsT[(i >> 2) * B_ + b0 + (i & 3)];
        }
        // cst[k][f] = cond_W[f0+f][k]; coalesced LDG, stride-33 conflict-free STS
        #pragma unroll
        for (int fr = 0; fr < 4; fr++) {
            int f = wi + fr * 8;
            const float* src = cond_W + (size_t)(f0 + f) * FEAT_;
            #pragma unroll
            for (int c = 0; c < 20; c++) {
                int k = c * 32 + lane;
                cst[k * 33 + f] = src[k];
            }
        }
        __syncthreads();

        const int pr = wi & 1, kq = wi >> 1;    // b-pair, K-quarter (160 each)
        const float* cb = cst + kq * 160 * 33 + lane;
        const float* fb = fs + kq * 160 * 4 + pr * 2;
        u64 acc = 0ull;
        #pragma unroll 8
        for (int kk = 0; kk < 160; kk++) {
            float w = cb[kk * 33];
            u64 fp = *reinterpret_cast<const u64*>(fb + kk * 4);
            fma2(acc, pack2(w, w), fp);
        }
        sp2[wi][lane] = acc;
        __syncthreads();

        if (wi < 2) {
            float x0,x1,y0,y1,z0,z1,w0,w1;
            unpack2(sp2[wi    ][lane], x0, x1);
            unpack2(sp2[wi + 2][lane], y0, y1);
            unpack2(sp2[wi + 4][lane], z0, z1);
            unpack2(sp2[wi + 6][lane], w0, w1);
            float cbv = cond_b[f0 + lane];
            float t0 = tanhf(((x0 + y0) + (z0 + w0)) + cbv);   // b = b0+wi*2
            float t1 = tanhf(((x1 + y1) + (z1 + w1)) + cbv);   // b = b0+wi*2+1
            // fused head: partial dot over this CTA's 32 f
            #pragma unroll
            for (int o = 0; o < 2; o++) {
                float lw = lin_W[o * F_ + f0 + lane];
                float q0 = t0 * lw, q1 = t1 * lw;
                #pragma unroll
                for (int off = 16; off; off >>= 1) {
                    q0 += __shfl_xor_sync(0xffffffffu, q0, off);
                    q1 += __shfl_xor_sync(0xffffffffu, q1, off);
                }
                if (lane == 0) {
                    float bias = (ft == 0) ? lin_b[o] : 0.0f;
                    atomicAdd(&out[(b0 + wi * 2)     * 2 + o], q0 + bias);
                    atomicAdd(&out[(b0 + wi * 2 + 1) * 2 + o], q1 + bias);
                }
            }
        }
    }
}

#define DYN_SMEM ((D_ * 64 + 32 * 257) * 4)   /* 98,432 B (phase 1 is max) */

extern "C" void kernel_launch(void* const* d_in, const int* in_sizes, int n_in,
                              void* d_out, int out_size)
{
    const int*   x       = (const int*)  d_in[0];
    const int*   ents    = (const int*)  d_in[1];
    const int*   spos    = (const int*)  d_in[2];
    const int*   tpos    = (const int*)  d_in[3];
    const float* emb     = (const float*)d_in[4];
    const float* ent_emb = (const float*)d_in[5];
    const float* attw_W  = (const float*)d_in[6];
    const float* attw_b  = (const float*)d_in[7];
    const float* attw2_W = (const float*)d_in[8];
    const float* cond_W  = (const float*)d_in[9];
    const float* cond_b  = (const float*)d_in[10];
    const float* lin_W   = (const float*)d_in[11];
    const float* lin_b   = (const float*)d_in[12];
    float* out = (float*)d_out;

    cudaFuncSetAttribute(fused_all, cudaFuncAttributeMaxDynamicSharedMemorySize, DYN_SMEM);
    fused_all<<<GRID_, NT_, DYN_SMEM>>>(x, ents, spos, tpos, emb, ent_emb,
                                        attw_W, attw_b, attw2_W,
                                        cond_W, cond_b, lin_W, lin_b, out);
}

// round 15
// speedup vs baseline: 1.2535x; 1.2535x over previous
#include <cuda_runtime.h>
#include <math.h>

#define S_  512
#define L_  128
#define D_  256
#define H2_ 128
#define P_  16
#define B_  128
#define F_  256
#define FEAT_ 640
#define ED_ 64
#define GRID_ 148
#define NT_ 512

typedef unsigned long long u64;

// Scratch (device globals — no allocations allowed)
__device__ float g_feats[B_ * FEAT_];   // [b][k]
__device__ unsigned g_flag[B_];         // per-b completion, monotonic across replays
__device__ unsigned g_tick;             // epoch ticket

__device__ __forceinline__ u64 pack2(float x, float y) {
    u64 r; asm("mov.b64 %0, {%1, %2};" : "=l"(r) : "f"(x), "f"(y)); return r;
}
__device__ __forceinline__ void unpack2(u64 v, float& x, float& y) {
    asm("mov.b64 {%0, %1}, %2;" : "=f"(x), "=f"(y) : "l"(v));
}
__device__ __forceinline__ void fma2(u64& d, u64 a, u64 b) {
    asm("fma.rn.f32x2 %0, %1, %2, %0;" : "+l"(d) : "l"(a), "l"(b));
}

__global__ __launch_bounds__(NT_, 1) void fused_all(
    const int* __restrict__ x,        // [S, L]
    const int* __restrict__ ents,     // [B, 2]
    const int* __restrict__ spos,     // [B, P, 2]
    const int* __restrict__ tpos,     // [B, P, 2]
    const float* __restrict__ emb,    // [V, D]
    const float* __restrict__ ent_emb,// [E_V, ED]
    const float* __restrict__ attw_W, // [H2, D]
    const float* __restrict__ attw_b, // [H2]
    const float* __restrict__ attw2_W,// [1, H2]
    const float* __restrict__ cond_W, // [F, FEAT]
    const float* __restrict__ cond_b, // [F]
    const float* __restrict__ lin_W,  // [2, F]
    const float* __restrict__ lin_b,  // [2]
    float* __restrict__ out)          // [B, 2]
{
    extern __shared__ float sm[];
    const int cta = blockIdx.x, tid = threadIdx.x;
    const int wi = tid >> 5, lane = tid & 31;

    __shared__ int      toks[32];
    __shared__ float    part[32][17];
    __shared__ float    logits[32];
    __shared__ float    wgt[32];
    __shared__ u64      sp2[16][32];
    __shared__ unsigned s_epoch;

    // epoch ticket (exactly GRID_ adds per replay -> epoch increments each run)
    if (tid == 0) s_epoch = atomicAdd(&g_tick, 1u) / GRID_ + 1u;

    if (cta >= B_) return;   // 128 worker CTAs; all resident (1/SM), no deadlock

    const int b = cta;
    float* ws = sm;                  // [128 h][64 d4] float4 = attw_W verbatim (128 KB)
    float* Hm = sm + D_ * H2_;       // [32 r][64 d4] float4, XOR-swizzled (32 KB)

    // ---- stage attw_W verbatim (coalesced both sides) + toks ----
    if (tid < 32) {
        int pool = tid >> 4, p = tid & 15;
        const int* pos = pool ? tpos : spos;
        int s = pos[(b * P_ + p) * 2 + 0];
        int l = pos[(b * P_ + p) * 2 + 1];
        toks[tid] = x[s * L_ + l];
    }
    {
        const float4* src = reinterpret_cast<const float4*>(attw_W);
        float4* dst = reinterpret_cast<float4*>(ws);
        #pragma unroll
        for (int j = 0; j < 16; j++) dst[tid + NT_ * j] = src[tid + NT_ * j];
    }
    __syncthreads();

    // ---- gather 32 embedding rows into swizzled Hm ----
    // float index for (r, d): r*256 + (((d>>2) ^ (r&7)) << 2) + (d&3)
    #pragma unroll
    for (int j = 0; j < 16; j++) {
        int i = tid + NT_ * j;          // 8192 items
        int r = i >> 8, d = i & 255;
        int idx = r * 256 + ((((d >> 2) ^ (r & 7))) << 2) + (d & 3);
        Hm[idx] = emb[(size_t)toks[r] * D_ + d];
    }
    __syncthreads();

    // ---- Phase B: row = lane (32), warp -> 8 h-cols; d-vectorized ----
    const int col0 = wi * 8;
    {
        const float4* Hm4 = reinterpret_cast<const float4*>(Hm) + lane * 64;
        const float4* wp  = reinterpret_cast<const float4*>(ws) + col0 * 64;
        const int swz = lane & 7;
        u64 acc[8];
        #pragma unroll
        for (int i = 0; i < 8; i++) acc[i] = 0ull;
        #pragma unroll 4
        for (int d4 = 0; d4 < 64; d4++) {
            float4 a4 = Hm4[d4 ^ swz];
            u64 a01 = pack2(a4.x, a4.y), a23 = pack2(a4.z, a4.w);
            #pragma unroll
            for (int hh = 0; hh < 8; hh++) {
                const ulonglong2 wq = *reinterpret_cast<const ulonglong2*>(wp + hh * 64 + d4);
                fma2(acc[hh], a01, wq.x);
                fma2(acc[hh], a23, wq.y);
            }
        }
        // tanh + attw2 weighting over this thread's 8 cols
        float cs_ = 0.f;
        #pragma unroll
        for (int hh = 0; hh < 8; hh++) {
            float lo, hi; unpack2(acc[hh], lo, hi);
            int c = col0 + hh;
            cs_ += tanhf((lo + hi) + attw_b[c]) * attw2_W[c];
        }
        part[lane][wi] = cs_;
    }
    __syncthreads();
    if (tid < 32) {
        float s = 0.f;
        #pragma unroll
        for (int q = 0; q < 16; q++) s += part[tid][q];
        logits[tid] = s;
    }
    __syncthreads();
    if (tid < 2) {
        int base = tid * 16;
        float mx = logits[base];
        #pragma unroll
        for (int p = 1; p < 16; p++) mx = fmaxf(mx, logits[base + p]);
        float e[16]; float sum = 0.f;
        #pragma unroll
        for (int p = 0; p < 16; p++) { e[p] = __expf(logits[base + p] - mx); sum += e[p]; }
        float inv = 1.f / sum;
        #pragma unroll
        for (int p = 0; p < 16; p++) wgt[base + p] = e[p] * inv;
    }
    __syncthreads();

    // ---- pooled feats -> g_feats[b][k] (coalesced) ----
    {
        int pool = tid >> 8, k = tid & 255;
        float v = 0.f;
        #pragma unroll
        for (int p = 0; p < 16; p++) {
            int r = pool * 16 + p;
            int idx = r * 256 + ((((k >> 2) ^ (r & 7))) << 2) + (k & 3);
            v += wgt[pool * 16 + p] * Hm[idx];
        }
        g_feats[b * FEAT_ + pool * D_ + k] = v;
    }
    if (tid < 128) {
        int eidx = ents[b * 2 + (tid >> 6)];
        g_feats[b * FEAT_ + 2 * D_ + tid] = ent_emb[(size_t)eidx * ED_ + (tid & 63)];
    }
    // out zeroing for this b (before any gemm atomics touch it; guarded by flag)
    if (tid < 2) out[b * 2 + tid] = 0.0f;

    // release: feats for this b complete
    __threadfence();
    __syncthreads();
    if (tid == 0) atomicAdd(&g_flag[b], 1u);

    // ================= Phase 2: gemm tile 8b x 32f + fused head =============
    const int bt = cta >> 3, ft = cta & 7;
    const int b0 = bt * 8, f0 = ft * 32;
    float* fs  = sm;                 // [640][10]  feats slice (25.6 KB)
    float* cst = sm + FEAT_ * 10;    // [640][33]  cond slice (84.5 KB) — inside old ws+Hm? fits: 6400+21120=27520 < 40960

    // stage cond tile first (no dependency) to overlap the flag waits
    #pragma unroll
    for (int fr = 0; fr < 2; fr++) {
        int f = wi + fr * 16;
        const float* src = cond_W + (size_t)(f0 + f) * FEAT_;
        #pragma unroll
        for (int c = 0; c < 20; c++) {
            int k = c * 32 + lane;
            cst[k * 33 + f] = src[k];
        }
    }

    // acquire: wait for the 8 producer b's
    if (tid == 0) {
        #pragma unroll
        for (int q = 0; q < 8; q++) {
            volatile unsigned* fl = &g_flag[b0 + q];
            while (*fl < s_epoch) { }
        }
        __threadfence();
    }
    __syncthreads();

    // stage feats slice [640][10-pitch]
    {
        int bb = wi >> 1, half = wi & 1;
        const float* src = g_feats + (size_t)(b0 + bb) * FEAT_;
        #pragma unroll
        for (int c = 0; c < 10; c++) {
            int k = half * 320 + c * 32 + lane;
            fs[k * 10 + bb] = src[k];
        }
    }
    __syncthreads();

    {
        const int pr = wi & 3, kq = wi >> 2;     // b-pair, K-quarter (160 each)
        const float* cb = cst + kq * 160 * 33 + lane;
        const float* fb = fs + kq * 160 * 10 + pr * 2;
        u64 acc = 0ull;
        #pragma unroll 8
        for (int kk = 0; kk < 160; kk++) {
            float w = cb[kk * 33];
            u64 fp = *reinterpret_cast<const u64*>(fb + kk * 10);
            fma2(acc, pack2(w, w), fp);
        }
        sp2[wi][lane] = acc;
    }
    __syncthreads();

    if (wi < 4) {
        float x0,x1,y0,y1,z0,z1,w0,w1;
        unpack2(sp2[wi     ][lane], x0, x1);
        unpack2(sp2[wi +  4][lane], y0, y1);
        unpack2(sp2[wi +  8][lane], z0, z1);
        unpack2(sp2[wi + 12][lane], w0, w1);
        float cbv = cond_b[f0 + lane];
        float t0 = tanhf(((x0 + y0) + (z0 + w0)) + cbv);   // b = b0 + 2wi
        float t1 = tanhf(((x1 + y1) + (z1 + w1)) + cbv);   // b = b0 + 2wi + 1
        #pragma unroll
        for (int o = 0; o < 2; o++) {
            float lw = lin_W[o * F_ + f0 + lane];
            float q0 = t0 * lw, q1 = t1 * lw;
            #pragma unroll
            for (int off = 16; off; off >>= 1) {
                q0 += __shfl_xor_sync(0xffffffffu, q0, off);
                q1 += __shfl_xor_sync(0xffffffffu, q1, off);
            }
            if (lane == 0) {
                float bias = (ft == 0) ? lin_b[o] : 0.0f;
                atomicAdd(&out[(b0 + wi * 2)     * 2 + o], q0 + bias);
                atomicAdd(&out[(b0 + wi * 2 + 1) * 2 + o], q1 + bias);
            }
        }
    }
}

#define DYN_SMEM ((D_ * H2_ + 32 * D_) * 4)   /* 163,840 B */

extern "C" void kernel_launch(void* const* d_in, const int* in_sizes, int n_in,
                              void* d_out, int out_size)
{
    const int*   x       = (const int*)  d_in[0];
    const int*   ents    = (const int*)  d_in[1];
    const int*   spos    = (const int*)  d_in[2];
    const int*   tpos    = (const int*)  d_in[3];
    const float* emb     = (const float*)d_in[4];
    const float* ent_emb = (const float*)d_in[5];
    const float* attw_W  = (const float*)d_in[6];
    const float* attw_b  = (const float*)d_in[7];
    const float* attw2_W = (const float*)d_in[8];
    const float* cond_W  = (const float*)d_in[9];
    const float* cond_b  = (const float*)d_in[10];
    const float* lin_W   = (const float*)d_in[11];
    const float* lin_b   = (const float*)d_in[12];
    float* out = (float*)d_out;

    cudaFuncSetAttribute(fused_all, cudaFuncAttributeMaxDynamicSharedMemorySize, DYN_SMEM);
    fused_all<<<GRID_, NT_, DYN_SMEM>>>(x, ents, spos, tpos, emb, ent_emb,
                                        attw_W, attw_b, attw2_W,
                                        cond_W, cond_b, lin_W, lin_b, out);
}

// round 17
// speedup vs baseline: 1.2757x; 1.0177x over previous
#include <cuda_runtime.h>
#include <math.h>
#include <cstdint>

#define S_  512
#define L_  128
#define D_  256
#define H2_ 128
#define P_  16
#define B_  128
#define F_  256
#define FEAT_ 640
#define ED_ 64
#define GRID_ 148
#define NT_ 512

typedef unsigned long long u64;

// Scratch (device globals — no allocations allowed)
__device__ float g_feats[B_ * FEAT_];   // [b][k]
__device__ unsigned g_flag[B_];         // per-b completion, monotonic across replays
__device__ unsigned g_tick;             // epoch ticket

__device__ __forceinline__ u64 pack2(float x, float y) {
    u64 r; asm("mov.b64 %0, {%1, %2};" : "=l"(r) : "f"(x), "f"(y)); return r;
}
__device__ __forceinline__ void unpack2(u64 v, float& x, float& y) {
    asm("mov.b64 {%0, %1}, %2;" : "=f"(x), "=f"(y) : "l"(v));
}
__device__ __forceinline__ void fma2(u64& d, u64 a, u64 b) {
    asm("fma.rn.f32x2 %0, %1, %2, %0;" : "+l"(d) : "l"(a), "l"(b));
}
__device__ __forceinline__ void cp16(uint32_t dst, const void* src) {
    asm volatile("cp.async.cg.shared.global [%0], [%1], 16;" :: "r"(dst), "l"(src));
}
__device__ __forceinline__ void cp4(uint32_t dst, const void* src) {
    asm volatile("cp.async.ca.shared.global [%0], [%1], 4;" :: "r"(dst), "l"(src));
}
__device__ __forceinline__ void cp_wait_all() {
    asm volatile("cp.async.wait_all;" ::: "memory");
}

__global__ __launch_bounds__(NT_, 1) void fused_all(
    const int* __restrict__ x,        // [S, L]
    const int* __restrict__ ents,     // [B, 2]
    const int* __restrict__ spos,     // [B, P, 2]
    const int* __restrict__ tpos,     // [B, P, 2]
    const float* __restrict__ emb,    // [V, D]
    const float* __restrict__ ent_emb,// [E_V, ED]
    const float* __restrict__ attw_W, // [H2, D]
    const float* __restrict__ attw_b, // [H2]
    const float* __restrict__ attw2_W,// [1, H2]
    const float* __restrict__ cond_W, // [F, FEAT]
    const float* __restrict__ cond_b, // [F]
    const float* __restrict__ lin_W,  // [2, F]
    const float* __restrict__ lin_b,  // [2]
    float* __restrict__ out)          // [B, 2]
{
    extern __shared__ float sm[];
    const int cta = blockIdx.x, tid = threadIdx.x;
    const int wi = tid >> 5, lane = tid & 31;

    __shared__ int      toks[32];
    __shared__ float    part[32][17];
    __shared__ float    wgt[32];
    __shared__ u64      sp2[16][32];
    __shared__ unsigned s_epoch;

    // epoch ticket (exactly GRID_ adds per replay -> epoch increments each run)
    if (tid == 0) s_epoch = atomicAdd(&g_tick, 1u) / GRID_ + 1u;

    if (cta >= B_) return;   // 128 worker CTAs, all resident (1/SM)

    const int b = cta;
    float* ws = sm;                  // [128 h][64 d4] float4 = attw_W verbatim (128 KB)
    float* Hm = sm + D_ * H2_;       // [32 r][64 d4] float4, XOR-swizzled (32 KB)
    uint32_t smb  = (uint32_t)__cvta_generic_to_shared(sm);
    uint32_t smHm = (uint32_t)__cvta_generic_to_shared(Hm);

    // ---- stage attw_W verbatim via cp.async (fire-and-forget) + toks ----
    #pragma unroll
    for (int j = 0; j < 16; j++) {
        int i = tid + NT_ * j;                 // 8192 float4
        cp16(smb + i * 16, reinterpret_cast<const float4*>(attw_W) + i);
    }
    if (tid < 32) {
        int pool = tid >> 4, p = tid & 15;
        const int* pos = pool ? tpos : spos;
        int s = pos[(b * P_ + p) * 2 + 0];
        int l = pos[(b * P_ + p) * 2 + 1];
        toks[tid] = x[s * L_ + l];
    }
    __syncthreads();   // toks visible

    // ---- gather 32 embedding rows into swizzled Hm via cp.async 16B ----
    // float4 slot for (r, d4): r*64 + (d4 ^ (r&7))
    #pragma unroll
    for (int j = 0; j < 4; j++) {
        int c = tid + NT_ * j;                 // 2048 float4 chunks
        int r = c >> 6, d4 = c & 63;
        uint32_t dst = smHm + (r * 64 + (d4 ^ (r & 7))) * 16;
        cp16(dst, emb + (size_t)toks[r] * D_ + d4 * 4);
    }
    cp_wait_all();
    __syncthreads();

    // ---- Phase B: row = lane (32), warp -> 8 h-cols; d-vectorized ----
    const int col0 = wi * 8;
    {
        const float4* Hm4 = reinterpret_cast<const float4*>(Hm) + lane * 64;
        const float4* wp  = reinterpret_cast<const float4*>(ws) + col0 * 64;
        const int swz = lane & 7;
        u64 acc[8];
        #pragma unroll
        for (int i = 0; i < 8; i++) acc[i] = 0ull;
        #pragma unroll 4
        for (int d4 = 0; d4 < 64; d4++) {
            float4 a4 = Hm4[d4 ^ swz];
            u64 a01 = pack2(a4.x, a4.y), a23 = pack2(a4.z, a4.w);
            #pragma unroll
            for (int hh = 0; hh < 8; hh++) {
                const ulonglong2 wq = *reinterpret_cast<const ulonglong2*>(wp + hh * 64 + d4);
                fma2(acc[hh], a01, wq.x);
                fma2(acc[hh], a23, wq.y);
            }
        }
        float cs_ = 0.f;
        #pragma unroll
        for (int hh = 0; hh < 8; hh++) {
            float lo, hi; unpack2(acc[hh], lo, hi);
            int c = col0 + hh;
            cs_ += tanhf((lo + hi) + attw_b[c]) * attw2_W[c];
        }
        part[lane][wi] = cs_;
    }
    __syncthreads();   // part ready; ws region now dead

    // ---- overlap: stage cond tile into dead ws region (cp.async 4B) ----
    const int bt = cta >> 3, ft = cta & 7;
    const int b0 = bt * 8, f0 = ft * 32;
    float* cst = sm;                  // [640][33]  (84.5 KB, inside ws)
    float* fs  = sm + FEAT_ * 33;     // [640][10]  (25.6 KB, inside ws)
    {
        #pragma unroll
        for (int fr = 0; fr < 2; fr++) {
            int f = wi + fr * 16;
            const float* src = cond_W + (size_t)(f0 + f) * FEAT_;
            #pragma unroll
            for (int c = 0; c < 20; c++) {
                int k = c * 32 + lane;          // coalesced global read
                cp4(smb + (k * 33 + f) * 4, src + k);
            }
        }
    }

    // ---- logits + softmax in warp 0 (16-lane butterflies per pool) ----
    if (wi == 0) {
        float s = 0.f;
        #pragma unroll
        for (int q = 0; q < 16; q++) s += part[lane][q];
        float mx = s;
        #pragma unroll
        for (int off = 8; off; off >>= 1) mx = fmaxf(mx, __shfl_xor_sync(0xffffffffu, mx, off));
        float e = __expf(s - mx);
        float sum = e;
        #pragma unroll
        for (int off = 8; off; off >>= 1) sum += __shfl_xor_sync(0xffffffffu, sum, off);
        wgt[lane] = e / sum;
    }
    __syncthreads();

    // ---- pooled feats -> g_feats[b][k] (coalesced) ----
    {
        int pool = tid >> 8, k = tid & 255;
        float v = 0.f;
        #pragma unroll
        for (int p = 0; p < 16; p++) {
            int r = pool * 16 + p;
            int idx = r * 256 + (((k >> 2) ^ (r & 7)) << 2) + (k & 3);
            v += wgt[pool * 16 + p] * Hm[idx];
        }
        g_feats[b * FEAT_ + pool * D_ + k] = v;
    }
    if (tid < 128) {
        int eidx = ents[b * 2 + (tid >> 6)];
        g_feats[b * FEAT_ + 2 * D_ + tid] = ent_emb[(size_t)eidx * ED_ + (tid & 63)];
    }
    if (tid < 2) out[b * 2 + tid] = 0.0f;

    // release: feats for this b complete (fence by all threads, then barrier, then flag)
    __threadfence();
    __syncthreads();
    if (tid == 0) atomicAdd(&g_flag[b], 1u);

    // ================= Phase 2: gemm tile 8b x 32f + fused head =============
    // acquire: wait for the 8 producer b's (cond cp.asyncs streaming meanwhile)
    if (tid == 0) {
        #pragma unroll
        for (int q = 0; q < 8; q++) {
            volatile unsigned* fl = &g_flag[b0 + q];
            while (*fl < s_epoch) { }
        }
        __threadfence();
    }
    cp_wait_all();     // cond tile landed
    __syncthreads();

    // stage feats slice [640][10-pitch]
    {
        int bb = wi >> 1, half = wi & 1;
        const float* src = g_feats + (size_t)(b0 + bb) * FEAT_;
        #pragma unroll
        for (int c = 0; c < 10; c++) {
            int k = half * 320 + c * 32 + lane;
            fs[k * 10 + bb] = src[k];
        }
    }
    __syncthreads();

    {
        const int pr = wi & 3, kq = wi >> 2;     // b-pair, K-quarter (160 each)
        const float* cb = cst + kq * 160 * 33 + lane;
        const float* fb = fs + kq * 160 * 10 + pr * 2;
        u64 acc = 0ull;
        #pragma unroll 8
        for (int kk = 0; kk < 160; kk++) {
            float w = cb[kk * 33];
            u64 fp = *reinterpret_cast<const u64*>(fb + kk * 10);
            fma2(acc, pack2(w, w), fp);
        }
        sp2[wi][lane] = acc;
    }
    __syncthreads();

    if (wi < 4) {
        float x0,x1,y0,y1,z0,z1,w0,w1;
        unpack2(sp2[wi     ][lane], x0, x1);
        unpack2(sp2[wi +  4][lane], y0, y1);
        unpack2(sp2[wi +  8][lane], z0, z1);
        unpack2(sp2[wi + 12][lane], w0, w1);
        float cbv = cond_b[f0 + lane];
        float t0 = tanhf(((x0 + y0) + (z0 + w0)) + cbv);   // b = b0 + 2wi
        float t1 = tanhf(((x1 + y1) + (z1 + w1)) + cbv);   // b = b0 + 2wi + 1
        #pragma unroll
        for (int o = 0; o < 2; o++) {
            float lw = lin_W[o * F_ + f0 + lane];
            float q0 = t0 * lw, q1 = t1 * lw;
            #pragma unroll
            for (int off = 16; off; off >>= 1) {
                q0 += __shfl_xor_sync(0xffffffffu, q0, off);
                q1 += __shfl_xor_sync(0xffffffffu, q1, off);
            }
            if (lane == 0) {
                float bias = (ft == 0) ? lin_b[o] : 0.0f;
                atomicAdd(&out[(b0 + wi * 2)     * 2 + o], q0 + bias);
                atomicAdd(&out[(b0 + wi * 2 + 1) * 2 + o], q1 + bias);
            }
        }
    }
}

#define DYN_SMEM ((D_ * H2_ + 32 * D_) * 4)   /* 163,840 B */

extern "C" void kernel_launch(void* const* d_in, const int* in_sizes, int n_in,
                              void* d_out, int out_size)
{
    const int*   x       = (const int*)  d_in[0];
    const int*   ents    = (const int*)  d_in[1];
    const int*   spos    = (const int*)  d_in[2];
    const int*   tpos    = (const int*)  d_in[3];
    const float* emb     = (const float*)d_in[4];
    const float* ent_emb = (const float*)d_in[5];
    const float* attw_W  = (const float*)d_in[6];
    const float* attw_b  = (const float*)d_in[7];
    const float* attw2_W = (const float*)d_in[8];
    const float* cond_W  = (const float*)d_in[9];
    const float* cond_b  = (const float*)d_in[10];
    const float* lin_W   = (const float*)d_in[11];
    const float* lin_b   = (const float*)d_in[12];
    float* out = (float*)d_out;

    cudaFuncSetAttribute(fused_all, cudaFuncAttributeMaxDynamicSharedMemorySize, DYN_SMEM);
    fused_all<<<GRID_, NT_, DYN_SMEM>>>(x, ents, spos, tpos, emb, ent_emb,
                                        attw_W, attw_b, attw2_W,
                                        cond_W, cond_b, lin_W, lin_b, out);
}